// round 16
// baseline (speedup 1.0000x reference)
#include <cuda_runtime.h>
#include <math.h>

#define BB 2
#define CC 5
#define DD 96
#define HH 128
#define WW 128
#define VV (DD*HH*WW)        /* 1572864 */
#define HALFV (VV/2)
#define NW (VV/32)           /* 49152 words per mask */
#define WROW (WW/32)         /* 4 words per row */
#define NMASK 16
#define KSUB 2048
#define NBUCK 4096
#define CANDCAP 8192
#define NPAIR 8              /* B * (C-1) */

/* ---------------- scratch (static device globals; no allocation) -------- */
__device__ unsigned g_rand[VV];          /* threefry word per voxel */
__device__ unsigned g_mask[NMASK][NW];
__device__ unsigned g_bnd[NMASK][NW];
__device__ int      g_hist[NMASK][NBUCK];
__device__ int      g_bndDone[NMASK];
__device__ int      g_maskCnt[NMASK];
__device__ int      g_bndTot[NMASK];
__device__ int      g_bStar[NMASK];
__device__ int      g_need[NMASK];
__device__ int      g_sure[NMASK];
__device__ int      g_candCnt[NMASK];
__device__ unsigned g_candKey[NMASK][CANDCAP];
__device__ int      g_candIdx[NMASK][CANDCAP];
__device__ float4   g_pts[NMASK][KSUB];
__device__ double   g_vols[BB][CC];
__device__ double   g_inter[BB][CC-1];
__device__ double   g_psum[BB][CC-1];
__device__ double   g_ce;
__device__ double   g_cham[2][NPAIR];

/* ---------------- threefry2x32-20, JAX semantics, key=(0,42) ------------ */
__device__ __forceinline__ unsigned rotl(unsigned x, int r){ return (x<<r)|(x>>(32-r)); }

__device__ __forceinline__ unsigned threefry_u32(int i){
    unsigned x0, x1;
    if (i < HALFV){ x0 = (unsigned)i;          x1 = (unsigned)(i + HALFV); }
    else          { x0 = (unsigned)(i - HALFV); x1 = (unsigned)i; }
    const unsigned ks0 = 0u, ks1 = 42u, ks2 = 0u ^ 42u ^ 0x1BD11BDAu;
    x0 += ks0; x1 += ks1;
#define TFR(r) { x0 += x1; x1 = rotl(x1,(r)); x1 ^= x0; }
    TFR(13) TFR(15) TFR(26) TFR(6)
    x0 += ks1; x1 += ks2 + 1u;
    TFR(17) TFR(29) TFR(16) TFR(24)
    x0 += ks2; x1 += ks0 + 2u;
    TFR(13) TFR(15) TFR(26) TFR(6)
    x0 += ks0; x1 += ks1 + 3u;
    TFR(17) TFR(29) TFR(16) TFR(24)
    x0 += ks1; x1 += ks2 + 4u;
    TFR(13) TFR(15) TFR(26) TFR(6)
    x0 += ks2; x1 += ks0 + 5u;
#undef TFR
    return (i < HALFV) ? x0 : x1;
}

/* ---------------- kernel 0: zero accumulators + precompute rand table --- */
__global__ void k_init(){
    int i = blockIdx.x*blockDim.x + threadIdx.x;
    int n = gridDim.x*blockDim.x;
    for (int v=i; v<VV; v+=n) g_rand[v] = threefry_u32(v);
    for (int k=i; k<NMASK*NBUCK; k+=n) ((int*)g_hist)[k]=0;
    for (int k=i; k<NMASK*KSUB; k+=n) ((float4*)g_pts)[k]=make_float4(0.f,0.f,0.f,0.f);
    if (i < NMASK){ g_maskCnt[i]=0; g_bndTot[i]=0; g_candCnt[i]=0; g_sure[i]=0; g_bStar[i]=-1; g_need[i]=0; g_bndDone[i]=0; }
    if (i < BB*CC) ((double*)g_vols)[i]=0.0;
    if (i < BB*(CC-1)){ ((double*)g_inter)[i]=0.0; ((double*)g_psum)[i]=0.0; }
    if (i < 2*NPAIR) ((double*)g_cham)[i]=0.0;
    if (i == 0) g_ce = 0.0;
}

/* ---------------- kernel 1: fused softmax / stats / bit-packed masks ----
   R11 version (measured 44.2us).                                         */
#define KM_G 1024
__global__ void __launch_bounds__(256, 5) k_main(const float* __restrict__ pred,
                                                 const float* __restrict__ tgt){
    int b = blockIdx.y;
    const float2* P2 = (const float2*)(pred + (size_t)b*CC*VV);
    const float2* T2 = (const float2*)(tgt  + (size_t)b*CC*VV);
    int lane = threadIdx.x & 31;
    unsigned grpMask = 0xFFFFu << ((lane>>4)*16);
    bool leader = (lane & 15) == 0;
    int sh = 2*(lane & 15);

    float acc[14];
#pragma unroll
    for (int k=0;k<14;k++) acc[k]=0.f;

#pragma unroll
    for (int it=0; it<3; it++){                 /* VV = 3 * KM_G*512 */
        int v  = it*(KM_G*512) + blockIdx.x*512 + threadIdx.x*2;
        int vi = v >> 1;
        float2 X[CC], T[CC];
#pragma unroll
        for (int c=0;c<CC;c++){
            X[c] = P2[c*(VV/2) + vi];
            T[c] = T2[c*(VV/2) + vi];
        }
        unsigned nibP0=0,nibP1=0,nibP2=0,nibP3=0;
        unsigned nibG0=0,nibG1=0,nibG2=0,nibG3=0;
#pragma unroll
        for (int j=0;j<2;j++){
            float x[CC], t[CC];
#pragma unroll
            for (int c=0;c<CC;c++){
                x[c] = j==0 ? X[c].x : X[c].y;
                t[c] = j==0 ? T[c].x : T[c].y;
            }
            float m = x[0];
#pragma unroll
            for (int c=1;c<CC;c++) m = fmaxf(m, x[c]);
            float e[CC], s = 0.f;
#pragma unroll
            for (int c=0;c<CC;c++){ e[c] = __expf(x[c]-m); s += e[c]; }
            float lse  = m + __logf(s);
            float sinv = __fdividef(1.f, s);
            float p[CC-1];
#pragma unroll
            for (int c=0;c<CC-1;c++) p[c] = e[c+1] * sinv;

            float xlab = x[0];
#pragma unroll
            for (int c=1;c<CC;c++) xlab = (t[c] > 0.5f) ? x[c] : xlab;
            acc[0] += lse - xlab;
#pragma unroll
            for (int c=0;c<4;c++){
                acc[1+c] += p[c];
                acc[5+c] += (t[c+1] > 0.5f) ? p[c] : 0.f;
            }
#pragma unroll
            for (int c=0;c<CC;c++) acc[9+c] += (t[c] > 0.5f) ? 1.f : 0.f;

            nibP0 |= (p[0] > 0.5f) ? (1u<<j) : 0u;
            nibP1 |= (p[1] > 0.5f) ? (1u<<j) : 0u;
            nibP2 |= (p[2] > 0.5f) ? (1u<<j) : 0u;
            nibP3 |= (p[3] > 0.5f) ? (1u<<j) : 0u;
            nibG0 |= (t[1] > 0.5f) ? (1u<<j) : 0u;
            nibG1 |= (t[2] > 0.5f) ? (1u<<j) : 0u;
            nibG2 |= (t[3] > 0.5f) ? (1u<<j) : 0u;
            nibG3 |= (t[4] > 0.5f) ? (1u<<j) : 0u;
        }
        int wi = v >> 5;
        unsigned w;
        w = __reduce_or_sync(grpMask, nibP0 << sh); if (leader) g_mask[b*4+0][wi] = w;
        w = __reduce_or_sync(grpMask, nibP1 << sh); if (leader) g_mask[b*4+1][wi] = w;
        w = __reduce_or_sync(grpMask, nibP2 << sh); if (leader) g_mask[b*4+2][wi] = w;
        w = __reduce_or_sync(grpMask, nibP3 << sh); if (leader) g_mask[b*4+3][wi] = w;
        w = __reduce_or_sync(grpMask, nibG0 << sh); if (leader) g_mask[8+b*4+0][wi] = w;
        w = __reduce_or_sync(grpMask, nibG1 << sh); if (leader) g_mask[8+b*4+1][wi] = w;
        w = __reduce_or_sync(grpMask, nibG2 << sh); if (leader) g_mask[8+b*4+2][wi] = w;
        w = __reduce_or_sync(grpMask, nibG3 << sh); if (leader) g_mask[8+b*4+3][wi] = w;
    }

#pragma unroll
    for (int o=16;o;o>>=1)
#pragma unroll
        for (int k=0;k<14;k++) acc[k] += __shfl_down_sync(0xffffffffu, acc[k], o);

    __shared__ float sR[14];
    if (threadIdx.x < 14) sR[threadIdx.x] = 0.f;
    __syncthreads();
    if (lane == 0){
#pragma unroll
        for (int k=0;k<14;k++) atomicAdd(&sR[k], acc[k]);
    }
    __syncthreads();
    if (threadIdx.x == 0){
        atomicAdd(&g_ce, (double)sR[0]);
#pragma unroll
        for (int c=0;c<4;c++){
            atomicAdd(&g_psum[b][c],  (double)sR[1+c]);
            atomicAdd(&g_inter[b][c], (double)sR[5+c]);
        }
#pragma unroll
        for (int c=0;c<CC;c++) atomicAdd(&g_vols[b][c], (double)sR[9+c]);
    }
}

/* ---------------- kernel 2: erosion + histogram + FUSED threshold ------- */
__global__ void k_bnd(){
    int mIdx = blockIdx.y;
    __shared__ int sh[NBUCK];
    for (int k=threadIdx.x; k<NBUCK; k+=1024) sh[k]=0;
    __syncthreads();

    const unsigned* M = g_mask[mIdx];
    int myCnt = 0;
#pragma unroll
    for (int kk=0; kk<3; kk++){
        int wi = blockIdx.x*3072 + kk*1024 + threadIdx.x;
        int d  = wi / (HH*WROW);
        int r  = wi - d*(HH*WROW);
        int h  = r / WROW;
        int wc = r - h*WROW;
        unsigned center = M[wi];
        unsigned er = 0xFFFFFFFFu;
#pragma unroll
        for (int dz=-1; dz<=1; dz++){
            int dd = d + dz;
            bool okd = (dd>=0 && dd<DD);
#pragma unroll
            for (int dy=-1; dy<=1; dy++){
                int hh = h + dy;
                unsigned tt = 0u;
                if (okd && hh>=0 && hh<HH){
                    int base = (dd*HH + hh)*WROW + wc;
                    unsigned mid = M[base];
                    unsigned lf  = (wc>0)       ? M[base-1] : 0u;
                    unsigned rt  = (wc<WROW-1)  ? M[base+1] : 0u;
                    tt = mid & ((mid<<1)|(lf>>31)) & ((mid>>1)|(rt<<31));
                }
                er &= tt;
            }
        }
        unsigned bnd = center & ~er;
        g_bnd[mIdx][wi] = bnd;
        myCnt += __popc(center);

        unsigned bb = bnd;
        const unsigned* R = g_rand + (wi << 5);
        while (bb){
            int bit = __ffs(bb)-1; bb &= bb-1;
            atomicAdd(&sh[R[bit] >> 20], 1);
        }
    }

#pragma unroll
    for (int o=16;o;o>>=1) myCnt += __shfl_down_sync(0xffffffffu, myCnt, o);
    if ((threadIdx.x & 31)==0 && myCnt) atomicAdd(&g_maskCnt[mIdx], myCnt);

    __syncthreads();
    for (int k=threadIdx.x; k<NBUCK; k+=1024){
        int c = sh[k];
        if (c) atomicAdd(&g_hist[mIdx][k], c);
    }

    /* ---- fused threshold: last block of this mask does the scan ---- */
    __threadfence();
    __syncthreads();
    __shared__ int isLast;
    if (threadIdx.x == 0) isLast = (atomicAdd(&g_bndDone[mIdx], 1) == 15) ? 1 : 0;
    __syncthreads();
    if (!isLast) return;

    __shared__ int arr[256];
    int t = threadIdx.x;
    int hloc[16];
    int hsum = 0;
    if (t < 256){
        int base = t*16;
#pragma unroll
        for (int j=0;j<16;j++){ hloc[j] = __ldcg(&g_hist[mIdx][base+j]); hsum += hloc[j]; }
        arr[t] = hsum;
    }
    __syncthreads();
#pragma unroll
    for (int o=1;o<256;o<<=1){
        int add = (t < 256 && t + o < 256) ? arr[t+o] : 0;
        __syncthreads();
        if (t < 256) arr[t] += add;
        __syncthreads();
    }
    int tot = arr[0];
    if (t == 0) g_bndTot[mIdx] = tot;
    if (tot <= KSUB) return;
    if (t < 256){
        int cum = arr[t] - hsum;
#pragma unroll
        for (int j=15;j>=0;j--){
            int c2 = cum + hloc[j];
            if (cum < KSUB && c2 >= KSUB){
                g_bStar[mIdx] = t*16 + j;
                g_need[mIdx]  = KSUB - cum;
            }
            cum = c2;
        }
    }
}

/* ---------------- kernel 3: BIT-PARALLEL warp-per-word selection --------
   One warp per mask word: lane handles bit=lane. Broadcast word load,
   coalesced rand load, ballot classification, one atomic per warp per
   class, popc-prefix placement. No serial bit loop, no second pass.
   Selection SETS identical (signed bu>bs keeps the bs=-1 all-sure path). */
__global__ void k_select(){
    int m = blockIdx.y;
    int gw = blockIdx.x*(blockDim.x>>5) + (threadIdx.x>>5);   /* word idx */
    int lane = threadIdx.x & 31;
    unsigned bb = g_bnd[m][gw];
    if (!bb) return;                     /* uniform per warp */
    int bs = g_bStar[m];
    int vbase = gw << 5;
    unsigned rb = g_rand[vbase + lane];  /* coalesced 128B */
    bool active = (bb >> lane) & 1u;
    int bu = (int)(rb >> 20);
    bool sure = active && (bu > bs);
    bool cand = active && (bu == bs);

    unsigned mS = __ballot_sync(0xffffffffu, sure);
    unsigned mC = __ballot_sync(0xffffffffu, cand);
    unsigned ltmask = (1u << lane) - 1u;

    if (mS){
        int ldr = __ffs(mS) - 1;
        int baseS = 0;
        if (lane == ldr) baseS = atomicAdd(&g_sure[m], __popc(mS));
        baseS = __shfl_sync(0xffffffffu, baseS, ldr);
        if (sure){
            int off = baseS + __popc(mS & ltmask);
            int v = vbase + lane;
            int dd = v >> 14;            /* HH*WW = 2^14 */
            int hh = (v >> 7) & 127;
            int ww = v & 127;
            g_pts[m][off] = make_float4((float)dd,(float)hh,(float)ww,1.f);
        }
    }
    if (mC){
        int ldr = __ffs(mC) - 1;
        int baseC = 0;
        if (lane == ldr) baseC = atomicAdd(&g_candCnt[m], __popc(mC));
        baseC = __shfl_sync(0xffffffffu, baseC, ldr);
        if (cand){
            int off = baseC + __popc(mC & ltmask);
            if (off < CANDCAP){
                g_candKey[m][off] = rb >> 9;
                g_candIdx[m][off] = vbase + lane;
            }
        }
    }
}

/* ---------------- kernel 4: exact rank inside cut bucket ---------------- */
__global__ void k_fincand(){
    int m = blockIdx.x;
    int need = g_need[m];
    if (need <= 0) return;
    int n = min(g_candCnt[m], CANDCAP);
    int base = g_sure[m];
    for (int i=threadIdx.x; i<n; i+=blockDim.x){
        unsigned ki = g_candKey[m][i];
        int ii = g_candIdx[m][i];
        int rank = 0;
        for (int j=0;j<n;j++){
            unsigned kj = g_candKey[m][j];
            if (kj > ki || (kj == ki && g_candIdx[m][j] < ii)) rank++;
        }
        if (rank < need){
            int v = ii;
            int dd = v/(HH*WW); int rr = v - dd*HH*WW; int hh = rr/WW; int ww = rr - hh*WW;
            g_pts[m][base + rank] = make_float4((float)dd,(float)hh,(float)ww,1.f);
        }
    }
}

/* ---------------- kernel 5: chamfer (R11 scalar fmaf version) ----------- */
__global__ void k_cham(){
    int dir  = blockIdx.y;
    int pair = blockIdx.z;
    int mq = dir ? 8 + pair : pair;
    int mr = dir ? pair     : 8 + pair;

    __shared__ float4 sref[KSUB];
    for (int k=threadIdx.x; k<KSUB; k+=blockDim.x){
        float4 rr = g_pts[mr][k];
        if (rr.w > 0.5f) rr.w = rr.x*rr.x + rr.y*rr.y + rr.z*rr.z;
        else { rr.x=0.f; rr.y=0.f; rr.z=0.f; rr.w=1e30f; }
        sref[k] = rr;
    }
    __syncthreads();

    int qi = blockIdx.x*blockDim.x + threadIdx.x;
    float4 q = g_pts[mq][qi];
    float contrib = 0.f;
    if (q.w > 0.5f){
        float q2  = q.x*q.x + q.y*q.y + q.z*q.z;
        float qx2 = -2.f*q.x, qy2 = -2.f*q.y, qz2 = -2.f*q.z;
        float m0=3.4e38f, m1=3.4e38f, m2=3.4e38f, m3=3.4e38f;
        for (int j=0;j<KSUB;j+=4){
            float4 r0=sref[j], r1=sref[j+1], r2=sref[j+2], r3=sref[j+3];
            float t0 = fmaf(r0.x, qx2, fmaf(r0.y, qy2, fmaf(r0.z, qz2, r0.w)));
            float t1 = fmaf(r1.x, qx2, fmaf(r1.y, qy2, fmaf(r1.z, qz2, r1.w)));
            float t2 = fmaf(r2.x, qx2, fmaf(r2.y, qy2, fmaf(r2.z, qz2, r2.w)));
            float t3 = fmaf(r3.x, qx2, fmaf(r3.y, qy2, fmaf(r3.z, qz2, r3.w)));
            m0 = fminf(m0,t0); m1 = fminf(m1,t1);
            m2 = fminf(m2,t2); m3 = fminf(m3,t3);
        }
        float tmin = fminf(fminf(m0,m1), fminf(m2,m3));
        contrib = sqrtf(fmaxf(tmin + q2, 0.f));
    }
    __shared__ float sbuf[256];
    sbuf[threadIdx.x] = contrib;
    __syncthreads();
    for (int o=128;o;o>>=1){
        if (threadIdx.x < o) sbuf[threadIdx.x] += sbuf[threadIdx.x + o];
        __syncthreads();
    }
    if (threadIdx.x == 0) atomicAdd(&g_cham[dir][pair], (double)sbuf[0]);
}

/* ---------------- kernel 6: combine everything -------------------------- */
__global__ void k_final(float* out){
    const float SW[5]   = {1.f, 2.f, 1.5f, 2.5f, 1.5f};
    const float BASE[5] = {0.f, 2000.f, 8000.f, 1000.f, 3000.f};

    float dw[BB][CC];
    for (int b=0;b<BB;b++){
        float eff[CC], mx = 0.f;
        for (int c=0;c<CC;c++){
            float vv = (float)g_vols[b][c];
            float mult = fminf(sqrtf(BASE[c] / fmaxf(vv, 1e-5f)), 2.5f);
            eff[c] = SW[c]*mult;
            mx = fmaxf(mx, eff[c]);
        }
        for (int c=0;c<CC;c++) dw[b][c] = eff[c] / fmaxf(mx, 1e-5f);
    }

    double diceSum = 0.0, tvSum = 0.0;
    for (int b=0;b<BB;b++)
        for (int c=0;c<4;c++){
            double I = g_inter[b][c], P = g_psum[b][c], G = g_vols[b][c+1];
            diceSum += 1.0 - (2.0*I + 1e-5) / (P + G + 1e-5);
            double fp = P - I, fn = G - I;
            tvSum   += 1.0 - (I + 1e-5) / (I + 0.3*fp + 0.7*fn + 1e-5);
        }
    double ce = g_ce / ((double)BB * (double)VV);
    double dice_ce = 0.5*(diceSum/8.0) + 0.5*ce;

    double ssum = 0.0;
    for (int b=0;b<BB;b++){
        double cs = 0.0; int nval = 0;
        for (int c=0;c<4;c++){
            int pc = g_maskCnt[b*4 + c];
            int gc = g_maskCnt[8 + b*4 + c];
            bool p0 = (pc==0), g0 = (gc==0);
            if (p0 && g0) continue;
            nval++;
            double w = (double)dw[b][c+1];
            if (p0 != g0){ cs += w*10.0; }
            else {
                int pair = b*4 + c;
                int np = min(g_bndTot[pair],     KSUB); if (np < 1) np = 1;
                int nt = min(g_bndTot[8 + pair], KSUB); if (nt < 1) nt = 1;
                double mp = g_cham[0][pair] / (double)np;
                double mt = g_cham[1][pair] / (double)nt;
                cs += w * 0.5 * (mp + mt);
            }
        }
        ssum += (nval > 0) ? cs / (double)nval : 0.0;
    }
    double total = 0.4*dice_ce + 0.4*(tvSum/8.0) + 0.2*(ssum/(double)BB);
    out[0] = (float)total;
}

/* ---------------- launch ------------------------------------------------ */
extern "C" void kernel_launch(void* const* d_in, const int* in_sizes, int n_in,
                              void* d_out, int out_size){
    const float* pred = (const float*)d_in[0];
    const float* tgt  = (const float*)d_in[1];
    float* out = (float*)d_out;

    k_init<<<1024, 256>>>();
    k_main<<<dim3(KM_G, BB), 256>>>(pred, tgt);
    k_bnd<<<dim3(16, NMASK), 1024>>>();          /* fused threshold */
    k_select<<<dim3(NW/32, NMASK), 1024>>>();    /* warp-per-word; 4th -> ncu */
    k_fincand<<<NMASK, 256>>>();
    k_cham<<<dim3(KSUB/256, 2, NPAIR), 256>>>();
    k_final<<<1, 1>>>(out);
}

// round 17
// speedup vs baseline: 1.4784x; 1.4784x over previous
#include <cuda_runtime.h>
#include <math.h>

#define BB 2
#define CC 5
#define DD 96
#define HH 128
#define WW 128
#define VV (DD*HH*WW)        /* 1572864 */
#define HALFV (VV/2)
#define NW (VV/32)           /* 49152 words per mask */
#define WROW (WW/32)         /* 4 words per row */
#define NMASK 16
#define KSUB 2048
#define NBUCK 4096
#define CANDCAP 8192
#define NPAIR 8              /* B * (C-1) */

/* ---------------- scratch (static device globals; no allocation) -------- */
__device__ unsigned g_rand[VV];          /* threefry word per voxel */
__device__ unsigned g_mask[NMASK][NW];
__device__ unsigned g_bnd[NMASK][NW];
__device__ int      g_hist[NMASK][NBUCK];
__device__ int      g_bndDone[NMASK];
__device__ int      g_maskCnt[NMASK];
__device__ int      g_bndTot[NMASK];
__device__ int      g_bStar[NMASK];
__device__ int      g_need[NMASK];
__device__ int      g_sure[NMASK];
__device__ int      g_candCnt[NMASK];
__device__ unsigned g_candKey[NMASK][CANDCAP];
__device__ int      g_candIdx[NMASK][CANDCAP];
__device__ float4   g_pts[NMASK][KSUB];
__device__ double   g_vols[BB][CC];
__device__ double   g_inter[BB][CC-1];
__device__ double   g_psum[BB][CC-1];
__device__ double   g_ce;
__device__ double   g_cham[2][NPAIR];

/* ---------------- threefry2x32-20, JAX semantics, key=(0,42) ------------ */
__device__ __forceinline__ unsigned rotl(unsigned x, int r){ return (x<<r)|(x>>(32-r)); }

__device__ __forceinline__ unsigned threefry_u32(int i){
    unsigned x0, x1;
    if (i < HALFV){ x0 = (unsigned)i;          x1 = (unsigned)(i + HALFV); }
    else          { x0 = (unsigned)(i - HALFV); x1 = (unsigned)i; }
    const unsigned ks0 = 0u, ks1 = 42u, ks2 = 0u ^ 42u ^ 0x1BD11BDAu;
    x0 += ks0; x1 += ks1;
#define TFR(r) { x0 += x1; x1 = rotl(x1,(r)); x1 ^= x0; }
    TFR(13) TFR(15) TFR(26) TFR(6)
    x0 += ks1; x1 += ks2 + 1u;
    TFR(17) TFR(29) TFR(16) TFR(24)
    x0 += ks2; x1 += ks0 + 2u;
    TFR(13) TFR(15) TFR(26) TFR(6)
    x0 += ks0; x1 += ks1 + 3u;
    TFR(17) TFR(29) TFR(16) TFR(24)
    x0 += ks1; x1 += ks2 + 4u;
    TFR(13) TFR(15) TFR(26) TFR(6)
    x0 += ks2; x1 += ks0 + 5u;
#undef TFR
    return (i < HALFV) ? x0 : x1;
}

/* ---------------- kernel 0: zero accumulators + precompute rand table --- */
__global__ void k_init(){
    int i = blockIdx.x*blockDim.x + threadIdx.x;
    int n = gridDim.x*blockDim.x;
    for (int v=i; v<VV; v+=n) g_rand[v] = threefry_u32(v);
    for (int k=i; k<NMASK*NBUCK; k+=n) ((int*)g_hist)[k]=0;
    for (int k=i; k<NMASK*KSUB; k+=n) ((float4*)g_pts)[k]=make_float4(0.f,0.f,0.f,0.f);
    if (i < NMASK){ g_maskCnt[i]=0; g_bndTot[i]=0; g_candCnt[i]=0; g_sure[i]=0; g_bStar[i]=-1; g_need[i]=0; g_bndDone[i]=0; }
    if (i < BB*CC) ((double*)g_vols)[i]=0.0;
    if (i < BB*(CC-1)){ ((double*)g_inter)[i]=0.0; ((double*)g_psum)[i]=0.0; }
    if (i < 2*NPAIR) ((double*)g_cham)[i]=0.0;
    if (i == 0) g_ce = 0.0;
}

/* ---------------- kernel 1: fused softmax / stats / bit-packed masks ----
   R11 version (measured 44.2us).                                         */
#define KM_G 1024
__global__ void __launch_bounds__(256, 5) k_main(const float* __restrict__ pred,
                                                 const float* __restrict__ tgt){
    int b = blockIdx.y;
    const float2* P2 = (const float2*)(pred + (size_t)b*CC*VV);
    const float2* T2 = (const float2*)(tgt  + (size_t)b*CC*VV);
    int lane = threadIdx.x & 31;
    unsigned grpMask = 0xFFFFu << ((lane>>4)*16);
    bool leader = (lane & 15) == 0;
    int sh = 2*(lane & 15);

    float acc[14];
#pragma unroll
    for (int k=0;k<14;k++) acc[k]=0.f;

#pragma unroll
    for (int it=0; it<3; it++){                 /* VV = 3 * KM_G*512 */
        int v  = it*(KM_G*512) + blockIdx.x*512 + threadIdx.x*2;
        int vi = v >> 1;
        float2 X[CC], T[CC];
#pragma unroll
        for (int c=0;c<CC;c++){
            X[c] = P2[c*(VV/2) + vi];
            T[c] = T2[c*(VV/2) + vi];
        }
        unsigned nibP0=0,nibP1=0,nibP2=0,nibP3=0;
        unsigned nibG0=0,nibG1=0,nibG2=0,nibG3=0;
#pragma unroll
        for (int j=0;j<2;j++){
            float x[CC], t[CC];
#pragma unroll
            for (int c=0;c<CC;c++){
                x[c] = j==0 ? X[c].x : X[c].y;
                t[c] = j==0 ? T[c].x : T[c].y;
            }
            float m = x[0];
#pragma unroll
            for (int c=1;c<CC;c++) m = fmaxf(m, x[c]);
            float e[CC], s = 0.f;
#pragma unroll
            for (int c=0;c<CC;c++){ e[c] = __expf(x[c]-m); s += e[c]; }
            float lse  = m + __logf(s);
            float sinv = __fdividef(1.f, s);
            float p[CC-1];
#pragma unroll
            for (int c=0;c<CC-1;c++) p[c] = e[c+1] * sinv;

            float xlab = x[0];
#pragma unroll
            for (int c=1;c<CC;c++) xlab = (t[c] > 0.5f) ? x[c] : xlab;
            acc[0] += lse - xlab;
#pragma unroll
            for (int c=0;c<4;c++){
                acc[1+c] += p[c];
                acc[5+c] += (t[c+1] > 0.5f) ? p[c] : 0.f;
            }
#pragma unroll
            for (int c=0;c<CC;c++) acc[9+c] += (t[c] > 0.5f) ? 1.f : 0.f;

            nibP0 |= (p[0] > 0.5f) ? (1u<<j) : 0u;
            nibP1 |= (p[1] > 0.5f) ? (1u<<j) : 0u;
            nibP2 |= (p[2] > 0.5f) ? (1u<<j) : 0u;
            nibP3 |= (p[3] > 0.5f) ? (1u<<j) : 0u;
            nibG0 |= (t[1] > 0.5f) ? (1u<<j) : 0u;
            nibG1 |= (t[2] > 0.5f) ? (1u<<j) : 0u;
            nibG2 |= (t[3] > 0.5f) ? (1u<<j) : 0u;
            nibG3 |= (t[4] > 0.5f) ? (1u<<j) : 0u;
        }
        int wi = v >> 5;
        unsigned w;
        w = __reduce_or_sync(grpMask, nibP0 << sh); if (leader) g_mask[b*4+0][wi] = w;
        w = __reduce_or_sync(grpMask, nibP1 << sh); if (leader) g_mask[b*4+1][wi] = w;
        w = __reduce_or_sync(grpMask, nibP2 << sh); if (leader) g_mask[b*4+2][wi] = w;
        w = __reduce_or_sync(grpMask, nibP3 << sh); if (leader) g_mask[b*4+3][wi] = w;
        w = __reduce_or_sync(grpMask, nibG0 << sh); if (leader) g_mask[8+b*4+0][wi] = w;
        w = __reduce_or_sync(grpMask, nibG1 << sh); if (leader) g_mask[8+b*4+1][wi] = w;
        w = __reduce_or_sync(grpMask, nibG2 << sh); if (leader) g_mask[8+b*4+2][wi] = w;
        w = __reduce_or_sync(grpMask, nibG3 << sh); if (leader) g_mask[8+b*4+3][wi] = w;
    }

#pragma unroll
    for (int o=16;o;o>>=1)
#pragma unroll
        for (int k=0;k<14;k++) acc[k] += __shfl_down_sync(0xffffffffu, acc[k], o);

    __shared__ float sR[14];
    if (threadIdx.x < 14) sR[threadIdx.x] = 0.f;
    __syncthreads();
    if (lane == 0){
#pragma unroll
        for (int k=0;k<14;k++) atomicAdd(&sR[k], acc[k]);
    }
    __syncthreads();
    if (threadIdx.x == 0){
        atomicAdd(&g_ce, (double)sR[0]);
#pragma unroll
        for (int c=0;c<4;c++){
            atomicAdd(&g_psum[b][c],  (double)sR[1+c]);
            atomicAdd(&g_inter[b][c], (double)sR[5+c]);
        }
#pragma unroll
        for (int c=0;c<CC;c++) atomicAdd(&g_vols[b][c], (double)sR[9+c]);
    }
}

/* ---------------- kernel 2: erosion + histogram + FUSED threshold ------- */
__global__ void k_bnd(){
    int mIdx = blockIdx.y;
    __shared__ int sh[NBUCK];
    for (int k=threadIdx.x; k<NBUCK; k+=1024) sh[k]=0;
    __syncthreads();

    const unsigned* M = g_mask[mIdx];
    int myCnt = 0;
#pragma unroll
    for (int kk=0; kk<3; kk++){
        int wi = blockIdx.x*3072 + kk*1024 + threadIdx.x;
        int d  = wi / (HH*WROW);
        int r  = wi - d*(HH*WROW);
        int h  = r / WROW;
        int wc = r - h*WROW;
        unsigned center = M[wi];
        unsigned er = 0xFFFFFFFFu;
#pragma unroll
        for (int dz=-1; dz<=1; dz++){
            int dd = d + dz;
            bool okd = (dd>=0 && dd<DD);
#pragma unroll
            for (int dy=-1; dy<=1; dy++){
                int hh = h + dy;
                unsigned tt = 0u;
                if (okd && hh>=0 && hh<HH){
                    int base = (dd*HH + hh)*WROW + wc;
                    unsigned mid = M[base];
                    unsigned lf  = (wc>0)       ? M[base-1] : 0u;
                    unsigned rt  = (wc<WROW-1)  ? M[base+1] : 0u;
                    tt = mid & ((mid<<1)|(lf>>31)) & ((mid>>1)|(rt<<31));
                }
                er &= tt;
            }
        }
        unsigned bnd = center & ~er;
        g_bnd[mIdx][wi] = bnd;
        myCnt += __popc(center);

        unsigned bb = bnd;
        const unsigned* R = g_rand + (wi << 5);
        while (bb){
            int bit = __ffs(bb)-1; bb &= bb-1;
            atomicAdd(&sh[R[bit] >> 20], 1);
        }
    }

#pragma unroll
    for (int o=16;o;o>>=1) myCnt += __shfl_down_sync(0xffffffffu, myCnt, o);
    if ((threadIdx.x & 31)==0 && myCnt) atomicAdd(&g_maskCnt[mIdx], myCnt);

    __syncthreads();
    for (int k=threadIdx.x; k<NBUCK; k+=1024){
        int c = sh[k];
        if (c) atomicAdd(&g_hist[mIdx][k], c);
    }

    /* ---- fused threshold: last block of this mask does the scan ---- */
    __threadfence();
    __syncthreads();
    __shared__ int isLast;
    if (threadIdx.x == 0) isLast = (atomicAdd(&g_bndDone[mIdx], 1) == 15) ? 1 : 0;
    __syncthreads();
    if (!isLast) return;

    __shared__ int arr[256];
    int t = threadIdx.x;
    int hloc[16];
    int hsum = 0;
    if (t < 256){
        int base = t*16;
#pragma unroll
        for (int j=0;j<16;j++){ hloc[j] = __ldcg(&g_hist[mIdx][base+j]); hsum += hloc[j]; }
        arr[t] = hsum;
    }
    __syncthreads();
#pragma unroll
    for (int o=1;o<256;o<<=1){
        int add = (t < 256 && t + o < 256) ? arr[t+o] : 0;
        __syncthreads();
        if (t < 256) arr[t] += add;
        __syncthreads();
    }
    int tot = arr[0];
    if (t == 0) g_bndTot[mIdx] = tot;
    if (tot <= KSUB) return;
    if (t < 256){
        int cum = arr[t] - hsum;
#pragma unroll
        for (int j=15;j>=0;j--){
            int c2 = cum + hloc[j];
            if (cum < KSUB && c2 >= KSUB){
                g_bStar[mIdx] = t*16 + j;
                g_need[mIdx]  = KSUB - cum;
            }
            cum = c2;
        }
    }
}

/* ---------------- kernel 3: warp-per-8-words bit-parallel selection -----
   Phase A: 8 bnd words per warp (one 32B coalesced load + shfl), 8 up-
   front rand loads (MLP=8), 16 ballots -> per-word masks + popc totals.
   ONE atomicAdd per class per warp (318-cyc return amortized over 8
   words). Phase B: popc-prefix placement with warp-uniform bases.
   Selection SETS identical; only g_pts order of sure picks permutes.    */
__global__ void k_select(){
    int m = blockIdx.y;
    int wid = threadIdx.x >> 5;
    int lane = threadIdx.x & 31;
    int w0 = (blockIdx.x*8 + wid) * 8;            /* first of 8 words */

    unsigned myw = (lane < 8) ? g_bnd[m][w0 + lane] : 0u;
    if (__ballot_sync(0xffffffffu, myw != 0u) == 0u) return;
    int bs = g_bStar[m];

    unsigned bbk[8], rb[8];
#pragma unroll
    for (int k=0;k<8;k++) bbk[k] = __shfl_sync(0xffffffffu, myw, k);
#pragma unroll
    for (int k=0;k<8;k++) rb[k] = bbk[k] ? g_rand[((w0+k)<<5) + lane] : 0u;

    unsigned mS[8], mC[8];
    int totS = 0, totC = 0;
#pragma unroll
    for (int k=0;k<8;k++){
        bool act = (bbk[k] >> lane) & 1u;
        int bu = (int)(rb[k] >> 20);
        mS[k] = __ballot_sync(0xffffffffu, act && (bu >  bs));
        mC[k] = __ballot_sync(0xffffffffu, act && (bu == bs));
        totS += __popc(mS[k]);
        totC += __popc(mC[k]);
    }

    int baseS = 0, baseC = 0;
    if (lane == 0){
        if (totS) baseS = atomicAdd(&g_sure[m],    totS);
        if (totC) baseC = atomicAdd(&g_candCnt[m], totC);
    }
    baseS = __shfl_sync(0xffffffffu, baseS, 0);
    baseC = __shfl_sync(0xffffffffu, baseC, 0);
    unsigned ltmask = (1u << lane) - 1u;

#pragma unroll
    for (int k=0;k<8;k++){
        if (mS[k]){
            if ((mS[k] >> lane) & 1u){
                int off = baseS + __popc(mS[k] & ltmask);
                int v = ((w0+k)<<5) + lane;
                g_pts[m][off] = make_float4((float)(v>>14),
                                            (float)((v>>7)&127),
                                            (float)(v&127), 1.f);
            }
            baseS += __popc(mS[k]);
        }
        if (mC[k]){
            if ((mC[k] >> lane) & 1u){
                int off = baseC + __popc(mC[k] & ltmask);
                if (off < CANDCAP){
                    g_candKey[m][off] = rb[k] >> 9;
                    g_candIdx[m][off] = ((w0+k)<<5) + lane;
                }
            }
            baseC += __popc(mC[k]);
        }
    }
}

/* ---------------- kernel 4: exact rank inside cut bucket ---------------- */
__global__ void k_fincand(){
    int m = blockIdx.x;
    int need = g_need[m];
    if (need <= 0) return;
    int n = min(g_candCnt[m], CANDCAP);
    int base = g_sure[m];
    for (int i=threadIdx.x; i<n; i+=blockDim.x){
        unsigned ki = g_candKey[m][i];
        int ii = g_candIdx[m][i];
        int rank = 0;
        for (int j=0;j<n;j++){
            unsigned kj = g_candKey[m][j];
            if (kj > ki || (kj == ki && g_candIdx[m][j] < ii)) rank++;
        }
        if (rank < need){
            int v = ii;
            int dd = v/(HH*WW); int rr = v - dd*HH*WW; int hh = rr/WW; int ww = rr - hh*WW;
            g_pts[m][base + rank] = make_float4((float)dd,(float)hh,(float)ww,1.f);
        }
    }
}

/* ---------------- kernel 5: chamfer (R11 scalar fmaf version) ----------- */
__global__ void k_cham(){
    int dir  = blockIdx.y;
    int pair = blockIdx.z;
    int mq = dir ? 8 + pair : pair;
    int mr = dir ? pair     : 8 + pair;

    __shared__ float4 sref[KSUB];
    for (int k=threadIdx.x; k<KSUB; k+=blockDim.x){
        float4 rr = g_pts[mr][k];
        if (rr.w > 0.5f) rr.w = rr.x*rr.x + rr.y*rr.y + rr.z*rr.z;
        else { rr.x=0.f; rr.y=0.f; rr.z=0.f; rr.w=1e30f; }
        sref[k] = rr;
    }
    __syncthreads();

    int qi = blockIdx.x*blockDim.x + threadIdx.x;
    float4 q = g_pts[mq][qi];
    float contrib = 0.f;
    if (q.w > 0.5f){
        float q2  = q.x*q.x + q.y*q.y + q.z*q.z;
        float qx2 = -2.f*q.x, qy2 = -2.f*q.y, qz2 = -2.f*q.z;
        float m0=3.4e38f, m1=3.4e38f, m2=3.4e38f, m3=3.4e38f;
        for (int j=0;j<KSUB;j+=4){
            float4 r0=sref[j], r1=sref[j+1], r2=sref[j+2], r3=sref[j+3];
            float t0 = fmaf(r0.x, qx2, fmaf(r0.y, qy2, fmaf(r0.z, qz2, r0.w)));
            float t1 = fmaf(r1.x, qx2, fmaf(r1.y, qy2, fmaf(r1.z, qz2, r1.w)));
            float t2 = fmaf(r2.x, qx2, fmaf(r2.y, qy2, fmaf(r2.z, qz2, r2.w)));
            float t3 = fmaf(r3.x, qx2, fmaf(r3.y, qy2, fmaf(r3.z, qz2, r3.w)));
            m0 = fminf(m0,t0); m1 = fminf(m1,t1);
            m2 = fminf(m2,t2); m3 = fminf(m3,t3);
        }
        float tmin = fminf(fminf(m0,m1), fminf(m2,m3));
        contrib = sqrtf(fmaxf(tmin + q2, 0.f));
    }
    __shared__ float sbuf[256];
    sbuf[threadIdx.x] = contrib;
    __syncthreads();
    for (int o=128;o;o>>=1){
        if (threadIdx.x < o) sbuf[threadIdx.x] += sbuf[threadIdx.x + o];
        __syncthreads();
    }
    if (threadIdx.x == 0) atomicAdd(&g_cham[dir][pair], (double)sbuf[0]);
}

/* ---------------- kernel 6: combine everything -------------------------- */
__global__ void k_final(float* out){
    const float SW[5]   = {1.f, 2.f, 1.5f, 2.5f, 1.5f};
    const float BASE[5] = {0.f, 2000.f, 8000.f, 1000.f, 3000.f};

    float dw[BB][CC];
    for (int b=0;b<BB;b++){
        float eff[CC], mx = 0.f;
        for (int c=0;c<CC;c++){
            float vv = (float)g_vols[b][c];
            float mult = fminf(sqrtf(BASE[c] / fmaxf(vv, 1e-5f)), 2.5f);
            eff[c] = SW[c]*mult;
            mx = fmaxf(mx, eff[c]);
        }
        for (int c=0;c<CC;c++) dw[b][c] = eff[c] / fmaxf(mx, 1e-5f);
    }

    double diceSum = 0.0, tvSum = 0.0;
    for (int b=0;b<BB;b++)
        for (int c=0;c<4;c++){
            double I = g_inter[b][c], P = g_psum[b][c], G = g_vols[b][c+1];
            diceSum += 1.0 - (2.0*I + 1e-5) / (P + G + 1e-5);
            double fp = P - I, fn = G - I;
            tvSum   += 1.0 - (I + 1e-5) / (I + 0.3*fp + 0.7*fn + 1e-5);
        }
    double ce = g_ce / ((double)BB * (double)VV);
    double dice_ce = 0.5*(diceSum/8.0) + 0.5*ce;

    double ssum = 0.0;
    for (int b=0;b<BB;b++){
        double cs = 0.0; int nval = 0;
        for (int c=0;c<4;c++){
            int pc = g_maskCnt[b*4 + c];
            int gc = g_maskCnt[8 + b*4 + c];
            bool p0 = (pc==0), g0 = (gc==0);
            if (p0 && g0) continue;
            nval++;
            double w = (double)dw[b][c+1];
            if (p0 != g0){ cs += w*10.0; }
            else {
                int pair = b*4 + c;
                int np = min(g_bndTot[pair],     KSUB); if (np < 1) np = 1;
                int nt = min(g_bndTot[8 + pair], KSUB); if (nt < 1) nt = 1;
                double mp = g_cham[0][pair] / (double)np;
                double mt = g_cham[1][pair] / (double)nt;
                cs += w * 0.5 * (mp + mt);
            }
        }
        ssum += (nval > 0) ? cs / (double)nval : 0.0;
    }
    double total = 0.4*dice_ce + 0.4*(tvSum/8.0) + 0.2*(ssum/(double)BB);
    out[0] = (float)total;
}

/* ---------------- launch ------------------------------------------------ */
extern "C" void kernel_launch(void* const* d_in, const int* in_sizes, int n_in,
                              void* d_out, int out_size){
    const float* pred = (const float*)d_in[0];
    const float* tgt  = (const float*)d_in[1];
    float* out = (float*)d_out;

    k_init<<<1024, 256>>>();
    k_main<<<dim3(KM_G, BB), 256>>>(pred, tgt);
    k_bnd<<<dim3(16, NMASK), 1024>>>();               /* fused threshold */
    k_select<<<dim3(NW/64, NMASK), 256>>>();          /* warp-per-8-words */
    k_fincand<<<NMASK, 256>>>();
    k_cham<<<dim3(KSUB/256, 2, NPAIR), 256>>>();
    k_final<<<1, 1>>>(out);
}